// round 1
// baseline (speedup 1.0000x reference)
#include <cuda_runtime.h>
#include <math.h>

#define L1V   16
#define NLM   136          // # (l,m) pairs with m<=l
#define NROWS 272          // cos rows [0,136) + sin rows [136,272)
#define BB    4
#define NPTS  8192
#define CIN   64
#define COUT  64
#define SLOPE 0.01f

// ---------------- scratch (device globals; no allocation) ----------------
__device__ float g_S[BB][NROWS][CIN];        // analysis sums
__device__ float g_T[BB][2][NLM][COUT];      // [b][0]=Tc = fac*Rre, [b][1]=Ts = -fac*Rim

__constant__ float c_inv[17] = {
    0.f, 1.f, 1.f/2.f, 1.f/3.f, 1.f/4.f, 1.f/5.f, 1.f/6.f, 1.f/7.f, 1.f/8.f,
    1.f/9.f, 1.f/10.f, 1.f/11.f, 1.f/12.f, 1.f/13.f, 1.f/14.f, 1.f/15.f, 1.f/16.f};

// ---------------- kernel 0: zero the S accumulator ----------------
__global__ void zero_S_kernel() {
    int i = blockIdx.x * blockDim.x + threadIdx.x;
    float* p = &g_S[0][0][0];
    if (i < BB * NROWS * CIN) p[i] = 0.f;
}

// ---------------- kernel 1: analysis ----------------
// S[b][row][c] = sum_n G[row][n] * values[b][n][c]
//   row r(l,m) (m-major): cos rows use G = P_lm * cos(m phi) * area,
//   sin rows (r+136) use G = P_lm * sin(m phi) * area.
// Grid: (NPTS/128, B). 256 threads. Register tile: thread(ty=tid/16,tx=tid%16)
// owns rows {ty+16j, j=0..16} x cols {4tx..4tx+3}  (17*4 = 68 accumulators).
#define AK_TK  16
#define AK_PTS 128

__global__ __launch_bounds__(256, 2)
void analysis_kernel(const float* __restrict__ theta, const float* __restrict__ phi,
                     const float* __restrict__ areas, const float* __restrict__ values)
{
    __shared__ float shG[NROWS][AK_TK + 1];   // +1 pad
    __shared__ float shV[AK_TK][CIN];
    __shared__ float shX[AK_TK], shS[AK_TK], shA[AK_TK], shPhi[AK_TK];

    const int b   = blockIdx.y;
    const int n0  = blockIdx.x * AK_PTS;
    const int tid = threadIdx.x;
    const int ty  = tid >> 4;          // 0..15
    const int tx  = tid & 15;          // 0..15

    float acc[17][4];
#pragma unroll
    for (int j = 0; j < 17; ++j) { acc[j][0] = acc[j][1] = acc[j][2] = acc[j][3] = 0.f; }

    for (int t = 0; t < AK_PTS / AK_TK; ++t) {
        const int nb = n0 + t * AK_TK;
        __syncthreads();   // previous tile fully consumed before overwrite

        if (tid < AK_TK) {
            float th = theta[b * NPTS + nb + tid];
            float x  = cosf(th);
            shX[tid]   = x;
            shS[tid]   = sqrtf(fmaxf(1.f - x * x, 0.f));
            shA[tid]   = areas[b * NPTS + nb + tid];
            shPhi[tid] = phi[b * NPTS + nb + tid];
        }
        {   // load values tile [16][64]: 256 threads x float4
            int k  = tid >> 4;
            int c4 = (tid & 15) * 4;
            float4 v = *(const float4*)&values[((size_t)b * NPTS + nb + k) * CIN + c4];
            *(float4*)&shV[k][c4] = v;
        }
        __syncthreads();

        {   // G generation: thread (k = tid&15, m = tid>>4)
            const int k = tid & 15, m = tid >> 4;
            float x = shX[k], s = shS[k], a = shA[k], ph = shPhi[k];
            float sm, cm;
            sincosf((float)m * ph, &sm, &cm);
            const float ca = cm * a, sa = sm * a;
            float pmm = 1.f;
            for (int i = 1; i <= m; ++i) pmm *= -(2.f * i - 1.f) * s;
            int r = m * L1V - (m * (m - 1)) / 2;   // base row for (l=m, m)
            float p_a = 0.f, p_b = pmm;
            float f2l1 = 2.f * m + 1.f;            // (2l+1) at l=m
            float flm  = 2.f * m;                  // (l+m)  at l=m
            for (int l = m; l < L1V; ++l) {
                shG[r][k]       = p_b * ca;
                shG[NLM + r][k] = p_b * sa;
                float pn = (f2l1 * x * p_b - flm * p_a) * c_inv[l + 1 - m];
                p_a = p_b; p_b = pn;
                f2l1 += 2.f; flm += 1.f; ++r;
            }
        }
        __syncthreads();

        // outer-product accumulation over the 16 points
#pragma unroll 4
        for (int k = 0; k < AK_TK; ++k) {
            float4 v = *(float4*)&shV[k][tx * 4];
#pragma unroll
            for (int j = 0; j < 17; ++j) {
                float g = shG[ty + 16 * j][k];
                acc[j][0] += g * v.x;
                acc[j][1] += g * v.y;
                acc[j][2] += g * v.z;
                acc[j][3] += g * v.w;
            }
        }
    }

    // flush partial tile
#pragma unroll
    for (int j = 0; j < 17; ++j) {
        float* dst = &g_S[b][ty + 16 * j][tx * 4];
        atomicAdd(dst + 0, acc[j][0]);
        atomicAdd(dst + 1, acc[j][1]);
        atomicAdd(dst + 2, acc[j][2]);
        atomicAdd(dst + 3, acc[j][3]);
    }
}

// ---------------- kernel 2: middle (W contraction + coeff + leaky relu) ----------------
// Grid (NLM, B), 64 threads (one per output channel d).
__global__ __launch_bounds__(64)
void middle_kernel(const float* __restrict__ W)
{
    const int b = blockIdx.y;
    const int r = blockIdx.x;           // 0..135
    const int d = threadIdx.x;

    // decode (l, m) from m-major row index
    int m = 0, base = 0;
    while (base + (L1V - m) <= r) { base += L1V - m; ++m; }
    const int l = m + (r - base);

    // coeff c[l,m] = 2*pi*sqrt(4*pi/(2l+1)) * (2l+1)*(l-m)!/(4*pi*(l+m)!)
    double pre  = 2.0 * M_PI * sqrt(4.0 * M_PI / (2.0 * l + 1.0));
    double sph2 = (2.0 * l + 1.0) / (4.0 * M_PI);
    for (int k = l - m + 1; k <= l + m; ++k) sph2 /= (double)k;
    const float clm = (float)(pre * sph2);

    __shared__ float Sc[CIN], Ss[CIN];
    Sc[d] = g_S[b][r][d];
    Ss[d] = g_S[b][NLM + r][d];
    __syncthreads();

    float are = 0.f, aim = 0.f;
    const float* Wl = W + l * CIN * COUT;
#pragma unroll 8
    for (int c = 0; c < CIN; ++c) {
        float w = Wl[c * COUT + d];
        are += Sc[c] * w;
        aim += Ss[c] * w;
    }
    are *=  clm;
    aim *= -clm;
    float rre = are > 0.f ? are : SLOPE * are;
    float rim = aim > 0.f ? aim : SLOPE * aim;
    const float fac = (m == 0) ? 1.f : 2.f;
    g_T[b][0][r][d] =  fac * rre;
    g_T[b][1][r][d] = -fac * rim;
}

// ---------------- kernel 3: synthesis ----------------
// out[b][n][d] = sum_r P_lm(n)*cos(m phi_n)*Tc[r][d] + P_lm(n)*sin(m phi_n)*Ts[r][d]
// Grid (NPTS/128, B), 256 threads: 2 threads per point, 32 channels each.
#define SK_PTS 128

__global__ __launch_bounds__(256)
void synthesis_kernel(const float* __restrict__ theta, const float* __restrict__ phi,
                      float* __restrict__ out)
{
    extern __shared__ float sh[];           // Tc[136*64] then Ts[136*64]
    float* Tc = sh;
    float* Ts = sh + NLM * COUT;

    const int b   = blockIdx.y;
    const int n0  = blockIdx.x * SK_PTS;
    const int tid = threadIdx.x;

    {   // load T for this batch
        const float4* src = (const float4*)&g_T[b][0][0][0];
        float4* dst = (float4*)sh;
        for (int i = tid; i < 2 * NLM * COUT / 4; i += 256) dst[i] = src[i];
    }
    __syncthreads();

    const int pt = tid >> 1;
    const int d0 = (tid & 1) * 32;
    const int n  = n0 + pt;

    const float th = theta[b * NPTS + n];
    const float ph = phi[b * NPTS + n];
    const float x  = cosf(th);
    const float s  = sqrtf(fmaxf(1.f - x * x, 0.f));
    float sphi, cphi;
    sincosf(ph, &sphi, &cphi);

    float acc[32];
#pragma unroll
    for (int i = 0; i < 32; ++i) acc[i] = 0.f;

    float cm = 1.f, sm = 0.f;     // cos(m phi), sin(m phi) at m=0
    float pmm = 1.f;              // P_mm at m=0
    int r = 0;
    for (int m = 0; m < L1V; ++m) {
        float p_a = 0.f, p_b = pmm;
        float f2l1 = 2.f * m + 1.f;
        float flm  = 2.f * m;
        for (int l = m; l < L1V; ++l) {
            const float gc = p_b * cm;
            const float gs = p_b * sm;
            const float* tc = &Tc[r * COUT + d0];
            const float* ts = &Ts[r * COUT + d0];
#pragma unroll
            for (int j = 0; j < 8; ++j) {
                float4 a4 = *(const float4*)&tc[4 * j];
                float4 b4 = *(const float4*)&ts[4 * j];
                acc[4 * j + 0] += gc * a4.x + gs * b4.x;
                acc[4 * j + 1] += gc * a4.y + gs * b4.y;
                acc[4 * j + 2] += gc * a4.z + gs * b4.z;
                acc[4 * j + 3] += gc * a4.w + gs * b4.w;
            }
            float pn = (f2l1 * x * p_b - flm * p_a) * c_inv[l + 1 - m];
            p_a = p_b; p_b = pn;
            f2l1 += 2.f; flm += 1.f; ++r;
        }
        pmm = -(2.f * m + 1.f) * s * pmm;       // P_{m+1,m+1}
        float cn = cm * cphi - sm * sphi;       // rotate trig
        float sn = sm * cphi + cm * sphi;
        cm = cn; sm = sn;
    }

    float* o = &out[((size_t)b * NPTS + n) * COUT + d0];
#pragma unroll
    for (int j = 0; j < 8; ++j) {
        *(float4*)&o[4 * j] = make_float4(acc[4 * j + 0], acc[4 * j + 1],
                                          acc[4 * j + 2], acc[4 * j + 3]);
    }
}

// ---------------- launch ----------------
extern "C" void kernel_launch(void* const* d_in, const int* in_sizes, int n_in,
                              void* d_out, int out_size)
{
    const float* theta  = (const float*)d_in[0];
    const float* phi    = (const float*)d_in[1];
    const float* areas  = (const float*)d_in[2];
    const float* values = (const float*)d_in[3];
    const float* W      = (const float*)d_in[4];
    float* out = (float*)d_out;

    const int syn_smem = 2 * NLM * COUT * (int)sizeof(float);   // 69632 B
    cudaFuncSetAttribute(synthesis_kernel,
                         cudaFuncAttributeMaxDynamicSharedMemorySize, syn_smem);

    zero_S_kernel<<<(BB * NROWS * CIN + 255) / 256, 256>>>();
    analysis_kernel<<<dim3(NPTS / AK_PTS, BB), 256>>>(theta, phi, areas, values);
    middle_kernel<<<dim3(NLM, BB), 64>>>(W);
    synthesis_kernel<<<dim3(NPTS / SK_PTS, BB), 256, syn_smem>>>(theta, phi, out);
}

// round 3
// speedup vs baseline: 1.1142x; 1.1142x over previous
#include <cuda_runtime.h>
#include <math.h>

#define L1V    16
#define NLM    136          // # (l,m) pairs with m<=l
#define NROWSP 288          // padded interleaved rows (272 used: k = 2*r_lm + {0=cos,1=sin})
#define BB     4
#define NPTS   8192
#define CIN    64
#define COUT   64
#define SLOPE  0.01f

// ---------------- scratch (device globals; no allocation) ----------------
__device__ float g_S[BB][NROWSP][CIN];       // analysis sums, interleaved rows
__device__ float g_T[BB][NLM][2][COUT];      // [r][0]=fac*Rre, [r][1]=-fac*Rim (interleaved)

__constant__ float c_inv[17] = {
    0.f, 1.f, 1.f/2.f, 1.f/3.f, 1.f/4.f, 1.f/5.f, 1.f/6.f, 1.f/7.f, 1.f/8.f,
    1.f/9.f, 1.f/10.f, 1.f/11.f, 1.f/12.f, 1.f/13.f, 1.f/14.f, 1.f/15.f, 1.f/16.f};

// ---------------- kernel 0: zero the S accumulator ----------------
__global__ void zero_S_kernel() {
    int i = blockIdx.x * blockDim.x + threadIdx.x;
    float* p = &g_S[0][0][0];
    if (i < BB * NROWSP * CIN) p[i] = 0.f;
}

// ---------------- kernel 1: analysis ----------------
// S[b][k][c] = sum_n G[k][n] * values[b][n][c],  k = 2*r_lm (cos) / 2*r_lm+1 (sin)
// Block: 256 points, all 288 (padded) rows, 64 ch. 288 threads, 8x8 per-thread tile.
#define AN_PTS 256
#define AN_KT  16
#define AN_THREADS 288

__global__ __launch_bounds__(AN_THREADS)
void analysis_kernel(const float* __restrict__ theta, const float* __restrict__ phi,
                     const float* __restrict__ areas, const float* __restrict__ values)
{
    __shared__ float shG[NROWSP][17];     // 17-pad kills bank conflicts on column reads
    __shared__ float shV[AN_KT][CIN];

    const int b   = blockIdx.y;
    const int n0  = blockIdx.x * AN_PTS;
    const int tid = threadIdx.x;
    const int ty  = tid >> 3;            // 0..35
    const int tx  = tid & 7;             // 0..7
    const int rowb = ty * 8;
    const int chb  = tx * 8;

    // zero the 16 pad rows once (never written by generation)
    if (tid < 272) shG[272 + tid / 17][tid % 17] = 0.f;

    float acc[8][8];
#pragma unroll
    for (int i = 0; i < 8; ++i)
#pragma unroll
        for (int j = 0; j < 8; ++j) acc[i][j] = 0.f;

    for (int t = 0; t < AN_PTS / AN_KT; ++t) {
        const int nb = n0 + t * AN_KT;
        __syncthreads();                 // previous tile fully consumed (also covers pad-zero)

        if (tid < 256) {                 // generation: thread (k = tid&15, m = tid>>4)
            const int k = tid & 15, m = tid >> 4;
            const int gi = b * NPTS + nb + k;
            float th = theta[gi];
            float x  = cosf(th);
            float s  = sqrtf(fmaxf(1.f - x * x, 0.f));
            float a  = areas[gi];
            float ph = phi[gi];
            float sm, cm;
            sincosf((float)m * ph, &sm, &cm);
            const float ca = cm * a, sa = sm * a;
            float pmm = 1.f;
            for (int i = 1; i <= m; ++i) pmm *= -(2.f * i - 1.f) * s;
            int r = m * L1V - (m * (m - 1)) / 2;
            float p_a = 0.f, p_b = pmm;
            float f2l1 = 2.f * m + 1.f;
            float flm  = 2.f * m;
            for (int l = m; l < L1V; ++l) {
                shG[2 * r][k]     = p_b * ca;
                shG[2 * r + 1][k] = p_b * sa;
                float pn = (f2l1 * x * p_b - flm * p_a) * c_inv[l + 1 - m];
                p_a = p_b; p_b = pn;
                f2l1 += 2.f; flm += 1.f; ++r;
            }
            // V tile load: 256 threads x float4 covers 16x64
            int vk = tid >> 4, c4 = (tid & 15) * 4;
            *(float4*)&shV[vk][c4] =
                *(const float4*)&values[((size_t)b * NPTS + nb + vk) * CIN + c4];
        }
        __syncthreads();

#pragma unroll 4
        for (int k = 0; k < AN_KT; ++k) {
            float g[8];
#pragma unroll
            for (int j = 0; j < 8; ++j) g[j] = shG[rowb + j][k];
            float4 v0 = *(float4*)&shV[k][chb];
            float4 v1 = *(float4*)&shV[k][chb + 4];
            float tv[8] = {v0.x, v0.y, v0.z, v0.w, v1.x, v1.y, v1.z, v1.w};
#pragma unroll
            for (int j = 0; j < 8; ++j)
#pragma unroll
                for (int jj = 0; jj < 8; ++jj)
                    acc[j][jj] += g[j] * tv[jj];
        }
    }

    if (rowb < 272) {
#pragma unroll
        for (int j = 0; j < 8; ++j)
#pragma unroll
            for (int jj = 0; jj < 8; ++jj)
                atomicAdd(&g_S[b][rowb + j][chb + jj], acc[j][jj]);
    }
}

// ---------------- kernel 2: middle (W contraction + coeff + leaky relu) ----------------
__global__ __launch_bounds__(64)
void middle_kernel(const float* __restrict__ W)
{
    const int b = blockIdx.y;
    const int r = blockIdx.x;           // 0..135
    const int d = threadIdx.x;

    int m = 0, base = 0;
    while (base + (L1V - m) <= r) { base += L1V - m; ++m; }
    const int l = m + (r - base);

    double pre  = 2.0 * M_PI * sqrt(4.0 * M_PI / (2.0 * l + 1.0));
    double sph2 = (2.0 * l + 1.0) / (4.0 * M_PI);
    for (int k = l - m + 1; k <= l + m; ++k) sph2 /= (double)k;
    const float clm = (float)(pre * sph2);

    __shared__ float Sc[CIN], Ss[CIN];
    Sc[d] = g_S[b][2 * r][d];
    Ss[d] = g_S[b][2 * r + 1][d];
    __syncthreads();

    float are = 0.f, aim = 0.f;
    const float* Wl = W + l * CIN * COUT;
#pragma unroll 8
    for (int c = 0; c < CIN; ++c) {
        float w = Wl[c * COUT + d];
        are += Sc[c] * w;
        aim += Ss[c] * w;
    }
    are *=  clm;
    aim *= -clm;
    float rre = are > 0.f ? are : SLOPE * are;
    float rim = aim > 0.f ? aim : SLOPE * aim;
    const float fac = (m == 0) ? 1.f : 2.f;
    g_T[b][r][0][d] =  fac * rre;
    g_T[b][r][1][d] = -fac * rim;
}

// ---------------- kernel 3: synthesis ----------------
// out[n][d] = sum_k G[k][n] * T[k][d], k interleaved cos/sin, K=272.
// Block: 256 points x 64 ch, 256 threads, 8x8 register tile.
// Per-thread serial Legendre/trig iterator (thread = point) emits 16-row G tiles.
#define SY_PTS 256
#define SY_KT  16

__global__ __launch_bounds__(256)
void synthesis_kernel(const float* __restrict__ theta, const float* __restrict__ phi,
                      float* __restrict__ out)
{
    extern __shared__ float sh[];
    float (*T)[COUT]   = (float(*)[COUT])sh;                       // [272][64]
    float (*G)[SY_PTS] = (float(*)[SY_PTS])(sh + 272 * COUT);      // [16][256]

    const int b   = blockIdx.y;
    const int n0  = blockIdx.x * SY_PTS;
    const int tid = threadIdx.x;

    {   // load T for this batch (g_T[b] is [136][2][64] = [272][64] interleaved, contiguous)
        const float4* src = (const float4*)&g_T[b][0][0][0];
        float4* dst = (float4*)sh;
        for (int i = tid; i < 272 * COUT / 4; i += 256) dst[i] = src[i];
    }

    // generator state (thread = point)
    const int n = n0 + tid;
    const float th = theta[b * NPTS + n];
    const float ph = phi[b * NPTS + n];
    const float x  = cosf(th);
    const float s  = sqrtf(fmaxf(1.f - x * x, 0.f));
    float sphi, cphi;
    sincosf(ph, &sphi, &cphi);
    float cm = 1.f, sm = 0.f, pmm = 1.f;
    float p_a = 0.f, p_b = 1.f, f2l1 = 1.f, flm = 0.f;
    int m = 0, l = 0;

    const int ty = tid >> 3, tx = tid & 7;
    const int ptb = ty * 8, chb = tx * 8;
    float acc[8][8];
#pragma unroll
    for (int i = 0; i < 8; ++i)
#pragma unroll
        for (int j = 0; j < 8; ++j) acc[i][j] = 0.f;

    for (int t = 0; t < 17; ++t) {
        // emit 8 recursion steps -> 16 G rows (cos,sin interleaved)
#pragma unroll
        for (int st = 0; st < 8; ++st) {
            G[2 * st][tid]     = p_b * cm;
            G[2 * st + 1][tid] = p_b * sm;
            float pn = (f2l1 * x * p_b - flm * p_a) * c_inv[l + 1 - m];
            p_a = p_b; p_b = pn;
            f2l1 += 2.f; flm += 1.f; ++l;
            if (l == L1V) {                      // next m-group (uniform across threads)
                pmm = -(2.f * m + 1.f) * s * pmm;
                ++m; l = m;
                float cn = cm * cphi - sm * sphi;
                sm = sm * cphi + cm * sphi; cm = cn;
                p_a = 0.f; p_b = pmm;
                f2l1 = 2.f * m + 1.f; flm = 2.f * m;
            }
        }
        __syncthreads();

        const int kb = t * SY_KT;
#pragma unroll 4
        for (int k = 0; k < SY_KT; ++k) {
            float4 g0 = *(float4*)&G[k][ptb];
            float4 g1 = *(float4*)&G[k][ptb + 4];
            float4 t0 = *(float4*)&T[kb + k][chb];
            float4 t1 = *(float4*)&T[kb + k][chb + 4];
            float gv[8] = {g0.x, g0.y, g0.z, g0.w, g1.x, g1.y, g1.z, g1.w};
            float tv[8] = {t0.x, t0.y, t0.z, t0.w, t1.x, t1.y, t1.z, t1.w};
#pragma unroll
            for (int i = 0; i < 8; ++i)
#pragma unroll
                for (int j = 0; j < 8; ++j)
                    acc[i][j] += gv[i] * tv[j];
        }
        __syncthreads();
    }

#pragma unroll
    for (int i = 0; i < 8; ++i) {
        float* o = &out[((size_t)b * NPTS + n0 + ptb + i) * COUT + chb];
        *(float4*)&o[0] = make_float4(acc[i][0], acc[i][1], acc[i][2], acc[i][3]);
        *(float4*)&o[4] = make_float4(acc[i][4], acc[i][5], acc[i][6], acc[i][7]);
    }
}

// ---------------- launch ----------------
extern "C" void kernel_launch(void* const* d_in, const int* in_sizes, int n_in,
                              void* d_out, int out_size)
{
    const float* theta  = (const float*)d_in[0];
    const float* phi    = (const float*)d_in[1];
    const float* areas  = (const float*)d_in[2];
    const float* values = (const float*)d_in[3];
    const float* W      = (const float*)d_in[4];
    float* out = (float*)d_out;

    const int syn_smem = (272 * COUT + SY_KT * SY_PTS) * (int)sizeof(float);  // 86016 B
    cudaFuncSetAttribute(synthesis_kernel,
                         cudaFuncAttributeMaxDynamicSharedMemorySize, syn_smem);

    zero_S_kernel<<<(BB * NROWSP * CIN + 255) / 256, 256>>>();
    analysis_kernel<<<dim3(NPTS / AN_PTS, BB), AN_THREADS>>>(theta, phi, areas, values);
    middle_kernel<<<dim3(NLM, BB), 64>>>(W);
    synthesis_kernel<<<dim3(NPTS / SY_PTS, BB), 256, syn_smem>>>(theta, phi, out);
}

// round 4
// speedup vs baseline: 1.1324x; 1.0164x over previous
#include <cuda_runtime.h>
#include <math.h>

#define L1V    16
#define NLM    136
#define NROWSP 288
#define BB     4
#define NPTS   8192
#define CIN    64
#define COUT   64
#define SLOPE  0.01f

// ---------------- scratch ----------------
__device__ float g_S[BB][NROWSP][CIN];       // analysis sums, interleaved rows (2r=cos,2r+1=sin)
__device__ float g_T[BB][NLM][2][COUT];      // [r][0]=fac*Rre, [r][1]=-fac*Rim

__constant__ float c_inv[17] = {
    0.f, 1.f, 1.f/2.f, 1.f/3.f, 1.f/4.f, 1.f/5.f, 1.f/6.f, 1.f/7.f, 1.f/8.f,
    1.f/9.f, 1.f/10.f, 1.f/11.f, 1.f/12.f, 1.f/13.f, 1.f/14.f, 1.f/15.f, 1.f/16.f};

// ---------------- f32x2 helpers ----------------
typedef unsigned long long ull;

__device__ __forceinline__ ull pk2(float x) {           // pack (x,x)
    ull r; asm("mov.b64 %0, {%1, %1};" : "=l"(r) : "f"(x)); return r;
}
__device__ __forceinline__ void fma2(ull& d, ull a, ull b) {
    asm("fma.rn.f32x2 %0, %1, %2, %3;" : "=l"(d) : "l"(a), "l"(b), "l"(d));
}
__device__ __forceinline__ float2 upk(ull v) {
    float2 f; asm("mov.b64 {%0, %1}, %2;" : "=f"(f.x), "=f"(f.y) : "l"(v)); return f;
}

// ---------------- kernel 0: zero S ----------------
__global__ void zero_S_kernel() {
    int i = blockIdx.x * blockDim.x + threadIdx.x;
    float* p = &g_S[0][0][0];
    if (i < BB * NROWSP * CIN) p[i] = 0.f;
}

// ---------------- kernel 1: analysis ----------------
// S[b][row][c] = sum_n G[row][n]*values[b][n][c]. Block: 128 pts, 288 rows(pad), 64 ch.
// 288 threads, per-thread 8 rows x 8 ch. G stored duplicated+interleaved:
// Gd[k][4r..] = (cos,cos), Gd[k][4r+2..] = (sin,sin). Double buffered.
#define AN_PTS 128
#define AN_KT  16
#define AN_GS  580                 // Gd row stride in floats (16B-aligned, low conflicts)

__global__ __launch_bounds__(288)
void analysis_kernel(const float* __restrict__ theta, const float* __restrict__ phi,
                     const float* __restrict__ areas, const float* __restrict__ values)
{
    extern __shared__ float sh[];
    float* Gd  = sh;                              // [2][AN_KT][AN_GS]
    float* Vt  = sh + 2 * AN_KT * AN_GS;          // [2][AN_KT][CIN]

    const int b   = blockIdx.y;
    const int n0  = blockIdx.x * AN_PTS;
    const int tid = threadIdx.x;
    const int ty  = tid >> 3;                     // 0..35
    const int tx  = tid & 7;
    const int rowb = ty * 8;
    const int chb  = tx * 8;

    ull acc[8][4];
#pragma unroll
    for (int i = 0; i < 8; ++i)
#pragma unroll
        for (int j = 0; j < 4; ++j) acc[i][j] = 0ull;

    // ---- emit helper (lambda-style via macro-free inline) ----
    auto emit = [&](int bu, int tile) {
        const int k = tid & 15, m = tid >> 4;     // tid < 256
        const int gi = b * NPTS + n0 + tile * AN_KT + k;
        float th = theta[gi];
        float x  = cosf(th);
        float s  = sqrtf(fmaxf(1.f - x * x, 0.f));
        float a  = areas[gi];
        float ph = phi[gi];
        float sm, cm;
        sincosf((float)m * ph, &sm, &cm);
        const float ca = cm * a, sa = sm * a;
        float pmm = 1.f;
        for (int i = 1; i <= m; ++i) pmm *= -(2.f * i - 1.f) * s;
        int r = m * L1V - (m * (m - 1)) / 2;
        float p_a = 0.f, p_b = pmm;
        float f2l1 = 2.f * m + 1.f;
        float flm  = 2.f * m;
        float* row = &Gd[bu * AN_KT * AN_GS + k * AN_GS];
        for (int l = m; l < L1V; ++l) {
            *(ull*)&row[4 * r]     = pk2(p_b * ca);
            *(ull*)&row[4 * r + 2] = pk2(p_b * sa);
            float pn = (f2l1 * x * p_b - flm * p_a) * c_inv[l + 1 - m];
            p_a = p_b; p_b = pn;
            f2l1 += 2.f; flm += 1.f; ++r;
        }
        // V tile: 256 threads x float4 covers 16x64
        int vk = tid >> 4, c4 = (tid & 15) * 4;
        *(float4*)&Vt[bu * AN_KT * CIN + vk * CIN + c4] =
            *(const float4*)&values[((size_t)b * NPTS + n0 + tile * AN_KT + vk) * CIN + c4];
    };

    if (tid < 256) emit(0, 0);
    __syncthreads();

    for (int t = 0; t < AN_PTS / AN_KT; ++t) {
        const int bu = t & 1;
        if (t + 1 < AN_PTS / AN_KT && tid < 256) emit(bu ^ 1, t + 1);

        const float* gbase = &Gd[bu * AN_KT * AN_GS];
        const float* vbase = &Vt[bu * AN_KT * CIN];
#pragma unroll 4
        for (int k = 0; k < AN_KT; ++k) {
            ulonglong2 v0 = *(const ulonglong2*)&vbase[k * CIN + chb];
            ulonglong2 v1 = *(const ulonglong2*)&vbase[k * CIN + chb + 4];
            const float* gp = &gbase[k * AN_GS + 2 * rowb];
            ulonglong2 gA = *(const ulonglong2*)(gp);
            ulonglong2 gB = *(const ulonglong2*)(gp + 4);
            ulonglong2 gC = *(const ulonglong2*)(gp + 8);
            ulonglong2 gD = *(const ulonglong2*)(gp + 12);
            fma2(acc[0][0], gA.x, v0.x); fma2(acc[0][1], gA.x, v0.y);
            fma2(acc[0][2], gA.x, v1.x); fma2(acc[0][3], gA.x, v1.y);
            fma2(acc[1][0], gA.y, v0.x); fma2(acc[1][1], gA.y, v0.y);
            fma2(acc[1][2], gA.y, v1.x); fma2(acc[1][3], gA.y, v1.y);
            fma2(acc[2][0], gB.x, v0.x); fma2(acc[2][1], gB.x, v0.y);
            fma2(acc[2][2], gB.x, v1.x); fma2(acc[2][3], gB.x, v1.y);
            fma2(acc[3][0], gB.y, v0.x); fma2(acc[3][1], gB.y, v0.y);
            fma2(acc[3][2], gB.y, v1.x); fma2(acc[3][3], gB.y, v1.y);
            fma2(acc[4][0], gC.x, v0.x); fma2(acc[4][1], gC.x, v0.y);
            fma2(acc[4][2], gC.x, v1.x); fma2(acc[4][3], gC.x, v1.y);
            fma2(acc[5][0], gC.y, v0.x); fma2(acc[5][1], gC.y, v0.y);
            fma2(acc[5][2], gC.y, v1.x); fma2(acc[5][3], gC.y, v1.y);
            fma2(acc[6][0], gD.x, v0.x); fma2(acc[6][1], gD.x, v0.y);
            fma2(acc[6][2], gD.x, v1.x); fma2(acc[6][3], gD.x, v1.y);
            fma2(acc[7][0], gD.y, v0.x); fma2(acc[7][1], gD.y, v0.y);
            fma2(acc[7][2], gD.y, v1.x); fma2(acc[7][3], gD.y, v1.y);
        }
        __syncthreads();
    }

    if (rowb < 272) {
#pragma unroll
        for (int j = 0; j < 8; ++j) {
            float2 a0 = upk(acc[j][0]), a1 = upk(acc[j][1]);
            float2 a2 = upk(acc[j][2]), a3 = upk(acc[j][3]);
            atomicAdd((float4*)&g_S[b][rowb + j][chb],
                      make_float4(a0.x, a0.y, a1.x, a1.y));
            atomicAdd((float4*)&g_S[b][rowb + j][chb + 4],
                      make_float4(a2.x, a2.y, a3.x, a3.y));
        }
    }
}

// ---------------- kernel 2: middle ----------------
__global__ __launch_bounds__(64)
void middle_kernel(const float* __restrict__ W)
{
    const int b = blockIdx.y;
    const int r = blockIdx.x;
    const int d = threadIdx.x;

    int m = 0, base = 0;
    while (base + (L1V - m) <= r) { base += L1V - m; ++m; }
    const int l = m + (r - base);

    double pre  = 2.0 * M_PI * sqrt(4.0 * M_PI / (2.0 * l + 1.0));
    double sph2 = (2.0 * l + 1.0) / (4.0 * M_PI);
    for (int k = l - m + 1; k <= l + m; ++k) sph2 /= (double)k;
    const float clm = (float)(pre * sph2);

    __shared__ float Sc[CIN], Ss[CIN];
    Sc[d] = g_S[b][2 * r][d];
    Ss[d] = g_S[b][2 * r + 1][d];
    __syncthreads();

    float are = 0.f, aim = 0.f;
    const float* Wl = W + l * CIN * COUT;
#pragma unroll 8
    for (int c = 0; c < CIN; ++c) {
        float w = Wl[c * COUT + d];
        are += Sc[c] * w;
        aim += Ss[c] * w;
    }
    are *=  clm;
    aim *= -clm;
    float rre = are > 0.f ? are : SLOPE * are;
    float rim = aim > 0.f ? aim : SLOPE * aim;
    const float fac = (m == 0) ? 1.f : 2.f;
    g_T[b][r][0][d] =  fac * rre;
    g_T[b][r][1][d] = -fac * rim;
}

// ---------------- kernel 3: synthesis ----------------
// out[n][d] = sum_k G[k][n]*T[k][d]. Block: 256 pts x 32 ch (half), 256 threads,
// per-thread 8 pts x 4 ch. G duplicated f32x2, double buffered, T resident.
#define SY_PTS 256
#define SY_KT  16
#define SY_CH  32

__global__ __launch_bounds__(256, 2)
void synthesis_kernel(const float* __restrict__ theta, const float* __restrict__ phi,
                      float* __restrict__ out)
{
    extern __shared__ float sh[];
    float* T  = sh;                               // [272][SY_CH]
    float* Gd = sh + 272 * SY_CH;                 // [2][SY_KT][2*SY_PTS]

    const int b     = blockIdx.y >> 1;
    const int choff = (blockIdx.y & 1) * SY_CH;
    const int n0    = blockIdx.x * SY_PTS;
    const int tid   = threadIdx.x;
    const int ty    = tid >> 3;                   // 0..31
    const int tx    = tid & 7;
    const int ptb   = ty * 8;
    const int chb   = tx * 4;

    {   // load T slice [272][32]
        const float* src = &g_T[b][0][0][0];      // [272][64] contiguous
        for (int i = tid; i < 272 * 8; i += 256) {
            int row = i >> 3, q = i & 7;
            *(float4*)&T[row * SY_CH + q * 4] =
                *(const float4*)&src[row * COUT + choff + q * 4];
        }
    }

    // generator state (thread = point)
    const int n = n0 + tid;
    const float th = theta[b * NPTS + n];
    const float ph = phi[b * NPTS + n];
    const float x  = cosf(th);
    const float s  = sqrtf(fmaxf(1.f - x * x, 0.f));
    float sphi, cphi;
    sincosf(ph, &sphi, &cphi);
    float cm = 1.f, sm = 0.f, pmm = 1.f;
    float p_a = 0.f, p_b = 1.f, f2l1 = 1.f, flm = 0.f;
    int m = 0, l = 0;

    auto emit8 = [&](int bu) {
        ull* g0 = (ull*)&Gd[bu * SY_KT * 2 * SY_PTS];
#pragma unroll
        for (int st = 0; st < 8; ++st) {
            g0[(2 * st)     * SY_PTS + tid] = pk2(p_b * cm);
            g0[(2 * st + 1) * SY_PTS + tid] = pk2(p_b * sm);
            float pn = (f2l1 * x * p_b - flm * p_a) * c_inv[l + 1 - m];
            p_a = p_b; p_b = pn;
            f2l1 += 2.f; flm += 1.f; ++l;
            if (l == L1V) {
                pmm = -(2.f * m + 1.f) * s * pmm;
                ++m; l = m;
                float cn = cm * cphi - sm * sphi;
                sm = sm * cphi + cm * sphi; cm = cn;
                p_a = 0.f; p_b = pmm;
                f2l1 = 2.f * m + 1.f; flm = 2.f * m;
            }
        }
    };

    ull acc[8][2];
#pragma unroll
    for (int i = 0; i < 8; ++i) { acc[i][0] = 0ull; acc[i][1] = 0ull; }

    emit8(0);
    __syncthreads();

    for (int t = 0; t < 17; ++t) {
        const int bu = t & 1;
        if (t < 16) emit8(bu ^ 1);

        const float* gbase = &Gd[bu * SY_KT * 2 * SY_PTS];
        const int kb = t * SY_KT;
#pragma unroll 4
        for (int k = 0; k < SY_KT; ++k) {
            ulonglong2 tv = *(const ulonglong2*)&T[(kb + k) * SY_CH + chb];
            const float* gp = &gbase[k * 2 * SY_PTS + 2 * ptb];
            ulonglong2 gA = *(const ulonglong2*)(gp);
            ulonglong2 gB = *(const ulonglong2*)(gp + 4);
            ulonglong2 gC = *(const ulonglong2*)(gp + 8);
            ulonglong2 gD = *(const ulonglong2*)(gp + 12);
            fma2(acc[0][0], gA.x, tv.x); fma2(acc[0][1], gA.x, tv.y);
            fma2(acc[1][0], gA.y, tv.x); fma2(acc[1][1], gA.y, tv.y);
            fma2(acc[2][0], gB.x, tv.x); fma2(acc[2][1], gB.x, tv.y);
            fma2(acc[3][0], gB.y, tv.x); fma2(acc[3][1], gB.y, tv.y);
            fma2(acc[4][0], gC.x, tv.x); fma2(acc[4][1], gC.x, tv.y);
            fma2(acc[5][0], gC.y, tv.x); fma2(acc[5][1], gC.y, tv.y);
            fma2(acc[6][0], gD.x, tv.x); fma2(acc[6][1], gD.x, tv.y);
            fma2(acc[7][0], gD.y, tv.x); fma2(acc[7][1], gD.y, tv.y);
        }
        __syncthreads();
    }

#pragma unroll
    for (int i = 0; i < 8; ++i) {
        float2 a0 = upk(acc[i][0]), a1 = upk(acc[i][1]);
        *(float4*)&out[((size_t)b * NPTS + n0 + ptb + i) * COUT + choff + chb] =
            make_float4(a0.x, a0.y, a1.x, a1.y);
    }
}

// ---------------- launch ----------------
extern "C" void kernel_launch(void* const* d_in, const int* in_sizes, int n_in,
                              void* d_out, int out_size)
{
    const float* theta  = (const float*)d_in[0];
    const float* phi    = (const float*)d_in[1];
    const float* areas  = (const float*)d_in[2];
    const float* values = (const float*)d_in[3];
    const float* W      = (const float*)d_in[4];
    float* out = (float*)d_out;

    const int an_smem = (2 * AN_KT * AN_GS + 2 * AN_KT * CIN) * (int)sizeof(float); // 82432
    const int sy_smem = (272 * SY_CH + 2 * SY_KT * 2 * SY_PTS) * (int)sizeof(float); // 100352
    cudaFuncSetAttribute(analysis_kernel,
                         cudaFuncAttributeMaxDynamicSharedMemorySize, an_smem);
    cudaFuncSetAttribute(synthesis_kernel,
                         cudaFuncAttributeMaxDynamicSharedMemorySize, sy_smem);

    zero_S_kernel<<<(BB * NROWSP * CIN + 255) / 256, 256>>>();
    analysis_kernel<<<dim3(NPTS / AN_PTS, BB), 288, an_smem>>>(theta, phi, areas, values);
    middle_kernel<<<dim3(NLM, BB), 64>>>(W);
    synthesis_kernel<<<dim3(NPTS / SY_PTS, 2 * BB), 256, sy_smem>>>(theta, phi, out);
}

// round 6
// speedup vs baseline: 1.7467x; 1.5425x over previous
#include <cuda_runtime.h>
#include <cuda_bf16.h>
#include <math.h>
#include <stdint.h>

#define L1V   16
#define NLM   136
#define BB    4
#define NPTS  8192
#define CIN   64
#define COUT  64
#define SLOPE 0.01f
#define SROWS 288          // 18 m-tiles of 16 (272 real)
#define KPAD  320          // synthesis K padded (5 chunks of 64)

// ---------------- scratch ----------------
__device__ float    g_S[BB][SROWS][CIN];
__device__ uint16_t g_Tt[BB][2][KPAD][COUT];   // bf16 [hi/lo][k][n]

__constant__ float c_inv[17] = {
    0.f, 1.f, 1.f/2.f, 1.f/3.f, 1.f/4.f, 1.f/5.f, 1.f/6.f, 1.f/7.f, 1.f/8.f,
    1.f/9.f, 1.f/10.f, 1.f/11.f, 1.f/12.f, 1.f/13.f, 1.f/14.f, 1.f/15.f, 1.f/16.f};

#define SWZ(o) ((o) ^ (((o) >> 3) & 0x70))

// ---------------- warp-MMA helpers (plain sm_100-safe) ----------------
__device__ __forceinline__ uint32_t smem_u32(const void* p) {
    uint32_t a;
    asm("{ .reg .u64 t; cvta.to.shared.u64 t, %1; cvt.u32.u64 %0, t; }" : "=r"(a) : "l"(p));
    return a;
}
__device__ __forceinline__ void ldsm4(uint32_t* r, uint32_t addr) {
    asm volatile("ldmatrix.sync.aligned.m8n8.x4.shared.b16 {%0,%1,%2,%3}, [%4];"
        : "=r"(r[0]), "=r"(r[1]), "=r"(r[2]), "=r"(r[3]) : "r"(addr));
}
__device__ __forceinline__ void ldsm4t(uint32_t* r, uint32_t addr) {
    asm volatile("ldmatrix.sync.aligned.m8n8.x4.trans.shared.b16 {%0,%1,%2,%3}, [%4];"
        : "=r"(r[0]), "=r"(r[1]), "=r"(r[2]), "=r"(r[3]) : "r"(addr));
}
__device__ __forceinline__ void mma16816(float* d, const uint32_t* a, const uint32_t* b) {
    asm volatile(
        "mma.sync.aligned.m16n8k16.row.col.f32.bf16.bf16.f32 "
        "{%0,%1,%2,%3}, {%4,%5,%6,%7}, {%8,%9}, {%0,%1,%2,%3};"
        : "+f"(d[0]), "+f"(d[1]), "+f"(d[2]), "+f"(d[3])
        : "r"(a[0]), "r"(a[1]), "r"(a[2]), "r"(a[3]), "r"(b[0]), "r"(b[1]));
}
__device__ __forceinline__ uint32_t pack_bf2(float a, float b) {
    __nv_bfloat162 h = __floats2bfloat162_rn(a, b);      // low half = a
    return *(uint32_t*)&h;
}
__device__ __forceinline__ void split_bf(float g, __nv_bfloat16& hi, __nv_bfloat16& lo) {
    hi = __float2bfloat16_rn(g);
    lo = __float2bfloat16_rn(g - __bfloat162float(hi));
}

// ---------------- kernel 0: zero scratch ----------------
__global__ void zero_kernel() {
    int i = blockIdx.x * blockDim.x + threadIdx.x;
    const int NS = BB * SROWS * CIN;                 // 73728 floats
    const int NT = BB * 2 * KPAD * COUT / 2;         // 81920 u32
    if (i < NS) ((float*)g_S)[i] = 0.f;
    else if (i < NS + NT) ((uint32_t*)g_Tt)[i - NS] = 0u;
}

// ---------------- kernel 1: analysis ----------------
// S[row][ch] += sum_pt G^T[row][pt] * V[pt][ch].  CTA: 256 pts (4 chunks of 64),
// 288 threads = 9 warps x 32 rows.  A=[288][64] bf16 SW128, B=[64][64] bf16 SW128.
__global__ __launch_bounds__(288)
void analysis_kernel(const float* __restrict__ theta, const float* __restrict__ phi,
                     const float* __restrict__ areas, const float* __restrict__ values)
{
    extern __shared__ __align__(1024) char sh[];
    char* Ah = sh;                 // 288*128 = 36864
    char* Al = sh + 36864;
    char* Bh = sh + 73728;         // 64*128 = 8192
    char* Bl = sh + 81920;         // total 90112
    const uint32_t AhU = smem_u32(Ah), AlU = smem_u32(Al);
    const uint32_t BhU = smem_u32(Bh), BlU = smem_u32(Bl);

    const int tid  = threadIdx.x;
    const int b    = blockIdx.y;
    const int n0   = blockIdx.x * 256;
    const int warp = tid >> 5, lane = tid & 31;

    float acc[2][8][4];
#pragma unroll
    for (int i = 0; i < 2; ++i)
#pragma unroll
        for (int j = 0; j < 8; ++j)
#pragma unroll
            for (int q = 0; q < 4; ++q) acc[i][j][q] = 0.f;

    for (int c = 0; c < 4; ++c) {
        __syncthreads();                       // previous chunk's mma done

        if (tid < 256) {
            // ---- generate A = G^T for 64 points ----
            const int pt = tid & 63, mg = tid >> 6;
            const int gi = b * NPTS + n0 + c * 64 + pt;
            const float th = theta[gi], ph = phi[gi], ar = areas[gi];
            const float x = cosf(th);
            const float s = sqrtf(fmaxf(1.f - x * x, 0.f));
#pragma unroll
            for (int mi = 0; mi < 4; ++mi) {
                const int m = mg + 4 * mi;
                float smv, cmv;
                sincosf((float)m * ph, &smv, &cmv);
                const float ca = cmv * ar, sa = smv * ar;
                float pmm = 1.f;
                for (int i = 1; i <= m; ++i) pmm *= -(2.f * i - 1.f) * s;
                int r = m * L1V - (m * (m - 1)) / 2;
                float pa = 0.f, pb = pmm;
                float f2 = 2.f * m + 1.f, fl = 2.f * m;
                for (int l = m; l < L1V; ++l) {
                    const float gc = pb * ca, gs = pb * sa;
                    __nv_bfloat16 chh, cll, shh, sll;
                    split_bf(gc, chh, cll);
                    split_bf(gs, shh, sll);
                    const int oc = SWZ((2 * r) * 128 + pt * 2);
                    const int os = SWZ((2 * r + 1) * 128 + pt * 2);
                    *(__nv_bfloat16*)(Ah + oc) = chh; *(__nv_bfloat16*)(Ah + os) = shh;
                    *(__nv_bfloat16*)(Al + oc) = cll; *(__nv_bfloat16*)(Al + os) = sll;
                    const float pn = (f2 * x * pb - fl * pa) * c_inv[l + 1 - m];
                    pa = pb; pb = pn; f2 += 2.f; fl += 1.f; ++r;
                }
            }
            // ---- B = V split, [pt][ch] SW128 ----
            const int vp = tid >> 2, cseg = (tid & 3) * 16;
            const float4* vsrc =
                (const float4*)&values[((size_t)b * NPTS + n0 + c * 64 + vp) * CIN + cseg];
#pragma unroll
            for (int q = 0; q < 4; ++q) {
                float4 v = vsrc[q];
                __nv_bfloat16 h0, l0, h1, l1, h2, l2, h3, l3;
                split_bf(v.x, h0, l0); split_bf(v.y, h1, l1);
                split_bf(v.z, h2, l2); split_bf(v.w, h3, l3);
                const int ch = cseg + q * 4;
                const int o0 = SWZ(vp * 128 + ch * 2);
                const int o1 = SWZ(vp * 128 + (ch + 2) * 2);
                *(uint32_t*)(Bh + o0) = pack_bf2(__bfloat162float(h0), __bfloat162float(h1));
                *(uint32_t*)(Bh + o1) = pack_bf2(__bfloat162float(h2), __bfloat162float(h3));
                *(uint32_t*)(Bl + o0) = pack_bf2(__bfloat162float(l0), __bfloat162float(l1));
                *(uint32_t*)(Bl + o1) = pack_bf2(__bfloat162float(l2), __bfloat162float(l3));
            }
        }
        __syncthreads();

        // ---- warp MMA: warp owns rows 32*warp..+31 (2 m-tiles) ----
#pragma unroll
        for (int kk = 0; kk < 4; ++kk) {
            uint32_t ah[2][4], al[2][4];
#pragma unroll
            for (int mt = 0; mt < 2; ++mt) {
                const int rowb = warp * 32 + mt * 16;
                const int aoff = SWZ((rowb + (lane & 15)) * 128 +
                                     (kk * 16 + 8 * (lane >> 4)) * 2);
                ldsm4(ah[mt], AhU + aoff);
                ldsm4(al[mt], AlU + aoff);
            }
#pragma unroll
            for (int ntp = 0; ntp < 4; ++ntp) {
                uint32_t bh[4], bl[4];
                const int boff = SWZ((kk * 16 + 8 * ((lane >> 3) & 1) + (lane & 7)) * 128 +
                                     (ntp * 16 + 8 * (lane >> 4)) * 2);
                ldsm4t(bh, BhU + boff);
                ldsm4t(bl, BlU + boff);
#pragma unroll
                for (int mt = 0; mt < 2; ++mt) {
                    mma16816(acc[mt][2 * ntp],     ah[mt], bh);
                    mma16816(acc[mt][2 * ntp],     ah[mt], bl);
                    mma16816(acc[mt][2 * ntp],     al[mt], bh);
                    mma16816(acc[mt][2 * ntp + 1], ah[mt], bh + 2);
                    mma16816(acc[mt][2 * ntp + 1], ah[mt], bl + 2);
                    mma16816(acc[mt][2 * ntp + 1], al[mt], bh + 2);
                }
            }
        }
    }

    // ---- epilogue: shfl-pair -> float4 atomics ----
#pragma unroll
    for (int mt = 0; mt < 2; ++mt) {
        const int row = warp * 32 + mt * 16 + (lane >> 2);
#pragma unroll
        for (int nt = 0; nt < 8; ++nt) {
            float* a = acc[mt][nt];
            float o0 = __shfl_down_sync(0xffffffffu, a[0], 1);
            float o1 = __shfl_down_sync(0xffffffffu, a[1], 1);
            float o2 = __shfl_down_sync(0xffffffffu, a[2], 1);
            float o3 = __shfl_down_sync(0xffffffffu, a[3], 1);
            if ((lane & 1) == 0) {
                const int col = nt * 8 + (lane & 2) * 2;     // 0 or 4
                if (row < 272)
                    atomicAdd((float4*)&g_S[b][row][col], make_float4(a[0], a[1], o0, o1));
                if (row + 8 < 272)
                    atomicAdd((float4*)&g_S[b][row + 8][col], make_float4(a[2], a[3], o2, o3));
            }
        }
    }
}

// ---------------- kernel 2: middle ----------------
__global__ __launch_bounds__(64)
void middle_kernel(const float* __restrict__ W)
{
    const int b = blockIdx.y;
    const int r = blockIdx.x;
    const int d = threadIdx.x;

    int m = 0, base = 0;
    while (base + (L1V - m) <= r) { base += L1V - m; ++m; }
    const int l = m + (r - base);

    double pre  = 2.0 * M_PI * sqrt(4.0 * M_PI / (2.0 * l + 1.0));
    double sph2 = (2.0 * l + 1.0) / (4.0 * M_PI);
    for (int k = l - m + 1; k <= l + m; ++k) sph2 /= (double)k;
    const float clm = (float)(pre * sph2);

    __shared__ float Sc[CIN], Ss[CIN];
    Sc[d] = g_S[b][2 * r][d];
    Ss[d] = g_S[b][2 * r + 1][d];
    __syncthreads();

    float are = 0.f, aim = 0.f;
    const float* Wl = W + l * CIN * COUT;
#pragma unroll 8
    for (int c = 0; c < CIN; ++c) {
        float w = Wl[c * COUT + d];
        are += Sc[c] * w;
        aim += Ss[c] * w;
    }
    are *=  clm;
    aim *= -clm;
    float rre = are > 0.f ? are : SLOPE * are;
    float rim = aim > 0.f ? aim : SLOPE * aim;
    const float fac = (m == 0) ? 1.f : 2.f;
    const float Tc =  fac * rre;
    const float Ts = -fac * rim;

    __nv_bfloat16 hc, lc, hs, ls;
    split_bf(Tc, hc, lc);
    split_bf(Ts, hs, ls);
    g_Tt[b][0][2 * r][d]     = *(uint16_t*)&hc;
    g_Tt[b][0][2 * r + 1][d] = *(uint16_t*)&hs;
    g_Tt[b][1][2 * r][d]     = *(uint16_t*)&lc;
    g_Tt[b][1][2 * r + 1][d] = *(uint16_t*)&ls;
}

// ---------------- kernel 3: synthesis ----------------
// out[pt][ch] = sum_k G[pt][k] * T[k][ch].  CTA: 128 pts, 256 threads (8 warps x 16 rows).
// Warps 0-3 generate A (thread=point), warps 4-7 copy B (T images); all warps mma.
__global__ __launch_bounds__(256)
void synthesis_kernel(const float* __restrict__ theta, const float* __restrict__ phi,
                      float* __restrict__ out)
{
    extern __shared__ __align__(1024) char sh[];
    char* Ah = sh;                 // 128*128 = 16384
    char* Al = sh + 16384;
    char* Bh = sh + 32768;         // 64*128 = 8192
    char* Bl = sh + 40960;         // total 49152
    const uint32_t AhU = smem_u32(Ah), AlU = smem_u32(Al);
    const uint32_t BhU = smem_u32(Bh), BlU = smem_u32(Bl);

    const int tid  = threadIdx.x;
    const int b    = blockIdx.y;
    const int n0   = blockIdx.x * 128;
    const int warp = tid >> 5, lane = tid & 31;

    // generator state (threads 0-127; thread = point)
    float x = 0.f, s = 0.f, sphi = 0.f, cphi = 0.f;
    float cm = 1.f, sm = 0.f, pmm = 1.f;
    float pa = 0.f, pb = 1.f, f2 = 1.f, fl = 0.f;
    int m = 0, l = 0, r = 0;
    if (tid < 128) {
        const int n = n0 + tid;
        const float th = theta[b * NPTS + n];
        const float ph = phi[b * NPTS + n];
        x = cosf(th);
        s = sqrtf(fmaxf(1.f - x * x, 0.f));
        sincosf(ph, &sphi, &cphi);
    }

    float acc[8][4];
#pragma unroll
    for (int j = 0; j < 8; ++j)
#pragma unroll
        for (int q = 0; q < 4; ++q) acc[j][q] = 0.f;

    for (int t = 0; t < 5; ++t) {
        __syncthreads();

        if (tid < 128) {
            // ---- generate 32 (cos,sin) k-pairs into A row ----
#pragma unroll
            for (int st = 0; st < 32; ++st) {
                const int off = SWZ(tid * 128 + st * 4);
                if (r < NLM) {
                    const float gc = pb * cm, gs = pb * sm;
                    __nv_bfloat16 chh, cll, shh, sll;
                    split_bf(gc, chh, cll);
                    split_bf(gs, shh, sll);
                    *(uint32_t*)(Ah + off) = pack_bf2(__bfloat162float(chh), __bfloat162float(shh));
                    *(uint32_t*)(Al + off) = pack_bf2(__bfloat162float(cll), __bfloat162float(sll));
                    const float pn = (f2 * x * pb - fl * pa) * c_inv[l + 1 - m];
                    pa = pb; pb = pn; f2 += 2.f; fl += 1.f; ++l; ++r;
                    if (l == L1V) {
                        pmm = -(2.f * m + 1.f) * s * pmm;
                        ++m; l = m;
                        const float cn = cm * cphi - sm * sphi;
                        sm = sm * cphi + cm * sphi; cm = cn;
                        pa = 0.f; pb = pmm;
                        f2 = 2.f * m + 1.f; fl = 2.f * m;
                    }
                } else {
                    *(uint32_t*)(Ah + off) = 0u;
                    *(uint32_t*)(Al + off) = 0u;
                }
            }
        } else {
            // ---- copy B chunk: 128 threads, one k-row of one split each ----
            const int loc = tid - 128;
            const int sp = loc >> 6, kr = loc & 63;
            const uint4* src = (const uint4*)&g_Tt[b][sp][t * 64 + kr][0];
            char* dst = sp ? Bl : Bh;
#pragma unroll
            for (int q = 0; q < 8; ++q)
                *(uint4*)(dst + SWZ(kr * 128 + q * 16)) = src[q];
        }
        __syncthreads();

        // ---- warp MMA: warp owns rows 16*warp..+15 ----
        const int ptb = warp * 16;
#pragma unroll
        for (int kk = 0; kk < 4; ++kk) {
            uint32_t ah[4], al[4];
            const int aoff = SWZ((ptb + (lane & 15)) * 128 +
                                 (kk * 16 + 8 * (lane >> 4)) * 2);
            ldsm4(ah, AhU + aoff);
            ldsm4(al, AlU + aoff);
#pragma unroll
            for (int ntp = 0; ntp < 4; ++ntp) {
                uint32_t bh[4], bl[4];
                const int boff = SWZ((kk * 16 + 8 * ((lane >> 3) & 1) + (lane & 7)) * 128 +
                                     (ntp * 16 + 8 * (lane >> 4)) * 2);
                ldsm4t(bh, BhU + boff);
                ldsm4t(bl, BlU + boff);
                mma16816(acc[2 * ntp],     ah, bh);
                mma16816(acc[2 * ntp],     ah, bl);
                mma16816(acc[2 * ntp],     al, bh);
                mma16816(acc[2 * ntp + 1], ah, bh + 2);
                mma16816(acc[2 * ntp + 1], ah, bl + 2);
                mma16816(acc[2 * ntp + 1], al, bh + 2);
            }
        }
    }

    // ---- epilogue: write D fragments ----
    const int g = lane >> 2, t4 = lane & 3;
    float* o0 = &out[((size_t)b * NPTS + n0 + warp * 16 + g) * COUT];
    float* o1 = &out[((size_t)b * NPTS + n0 + warp * 16 + g + 8) * COUT];
#pragma unroll
    for (int nt = 0; nt < 8; ++nt) {
        *(float2*)&o0[nt * 8 + 2 * t4] = make_float2(acc[nt][0], acc[nt][1]);
        *(float2*)&o1[nt * 8 + 2 * t4] = make_float2(acc[nt][2], acc[nt][3]);
    }
}

// ---------------- launch ----------------
extern "C" void kernel_launch(void* const* d_in, const int* in_sizes, int n_in,
                              void* d_out, int out_size)
{
    const float* theta  = (const float*)d_in[0];
    const float* phi    = (const float*)d_in[1];
    const float* areas  = (const float*)d_in[2];
    const float* values = (const float*)d_in[3];
    const float* W      = (const float*)d_in[4];
    float* out = (float*)d_out;

    const int an_smem = 90112;
    const int sy_smem = 49152;
    cudaFuncSetAttribute(analysis_kernel,
                         cudaFuncAttributeMaxDynamicSharedMemorySize, an_smem);
    cudaFuncSetAttribute(synthesis_kernel,
                         cudaFuncAttributeMaxDynamicSharedMemorySize, sy_smem);

    const int ztot = BB * SROWS * CIN + BB * 2 * KPAD * COUT / 2;
    zero_kernel<<<(ztot + 255) / 256, 256>>>();
    analysis_kernel<<<dim3(NPTS / 256, BB), 288, an_smem>>>(theta, phi, areas, values);
    middle_kernel<<<dim3(NLM, BB), 64>>>(W);
    synthesis_kernel<<<dim3(NPTS / 128, BB), 256, sy_smem>>>(theta, phi, out);
}

// round 8
// speedup vs baseline: 2.1368x; 1.2233x over previous
#include <cuda_runtime.h>
#include <cuda_bf16.h>
#include <math.h>
#include <stdint.h>

#define L1V   16
#define NLM   136
#define BB    4
#define NPTS  8192
#define CIN   64
#define COUT  64
#define SLOPE 0.01f
#define SROWS 272          // 17 m-tiles of 16, exact
#define KPAD  320          // synthesis K padded (5 chunks of 64)

// ---------------- scratch ----------------
__device__ float    g_S[BB][SROWS][CIN];
__device__ uint16_t g_Tt[BB][2][KPAD][COUT];   // bf16 [hi/lo][k][n]

__constant__ float c_inv[17] = {
    0.f, 1.f, 1.f/2.f, 1.f/3.f, 1.f/4.f, 1.f/5.f, 1.f/6.f, 1.f/7.f, 1.f/8.f,
    1.f/9.f, 1.f/10.f, 1.f/11.f, 1.f/12.f, 1.f/13.f, 1.f/14.f, 1.f/15.f, 1.f/16.f};

#define SWZ(o) ((o) ^ (((o) >> 3) & 0x70))

// ---------------- warp-MMA helpers ----------------
__device__ __forceinline__ uint32_t smem_u32(const void* p) {
    uint32_t a;
    asm("{ .reg .u64 t; cvta.to.shared.u64 t, %1; cvt.u32.u64 %0, t; }" : "=r"(a) : "l"(p));
    return a;
}
__device__ __forceinline__ void ldsm4(uint32_t* r, uint32_t addr) {
    asm volatile("ldmatrix.sync.aligned.m8n8.x4.shared.b16 {%0,%1,%2,%3}, [%4];"
        : "=r"(r[0]), "=r"(r[1]), "=r"(r[2]), "=r"(r[3]) : "r"(addr));
}
__device__ __forceinline__ void ldsm4t(uint32_t* r, uint32_t addr) {
    asm volatile("ldmatrix.sync.aligned.m8n8.x4.trans.shared.b16 {%0,%1,%2,%3}, [%4];"
        : "=r"(r[0]), "=r"(r[1]), "=r"(r[2]), "=r"(r[3]) : "r"(addr));
}
__device__ __forceinline__ void mma16816(float* d, const uint32_t* a, const uint32_t* b) {
    asm volatile(
        "mma.sync.aligned.m16n8k16.row.col.f32.bf16.bf16.f32 "
        "{%0,%1,%2,%3}, {%4,%5,%6,%7}, {%8,%9}, {%0,%1,%2,%3};"
        : "+f"(d[0]), "+f"(d[1]), "+f"(d[2]), "+f"(d[3])
        : "r"(a[0]), "r"(a[1]), "r"(a[2]), "r"(a[3]), "r"(b[0]), "r"(b[1]));
}
__device__ __forceinline__ uint32_t pack_bf2(float a, float b) {
    __nv_bfloat162 h = __floats2bfloat162_rn(a, b);      // low half = a
    return *(uint32_t*)&h;
}
__device__ __forceinline__ void split_bf(float g, __nv_bfloat16& hi, __nv_bfloat16& lo) {
    hi = __float2bfloat16_rn(g);
    lo = __float2bfloat16_rn(g - __bfloat162float(hi));
}

// ---------------- kernel 0: zero scratch ----------------
__global__ void zero_kernel() {
    int i = blockIdx.x * blockDim.x + threadIdx.x;
    const int NS = BB * SROWS * CIN;                 // 69632 floats
    const int NT = BB * 2 * KPAD * COUT / 2;         // 81920 u32
    if (i < NS) ((float*)g_S)[i] = 0.f;
    else if (i < NS + NT) ((uint32_t*)g_Tt)[i - NS] = 0u;
}

// ---------------- kernel 1: analysis ----------------
// S[row][ch] += sum_pt G^T[row][pt] * V[pt][ch].  CTA: 128 pts (2 chunks of 64),
// 544 threads = 17 warps x 16 rows.  Gen: 512 threads, (pt, mg) with m in {mg, 15-mg}
// -> exactly 17 recursion steps per thread.
__global__ __launch_bounds__(544)
void analysis_kernel(const float* __restrict__ theta, const float* __restrict__ phi,
                     const float* __restrict__ areas, const float* __restrict__ values)
{
    extern __shared__ __align__(1024) char sh[];
    char* Ah = sh;                 // 272*128 = 34816
    char* Al = sh + 34816;
    char* Bh = sh + 69632;         // 64*128 = 8192
    char* Bl = sh + 77824;         // total 86016
    const uint32_t AhU = smem_u32(Ah), AlU = smem_u32(Al);
    const uint32_t BhU = smem_u32(Bh), BlU = smem_u32(Bl);

    const int tid  = threadIdx.x;
    const int b    = blockIdx.y;
    const int n0   = blockIdx.x * 128;
    const int warp = tid >> 5, lane = tid & 31;

    float acc[8][4];
#pragma unroll
    for (int j = 0; j < 8; ++j)
#pragma unroll
        for (int q = 0; q < 4; ++q) acc[j][q] = 0.f;

    for (int c = 0; c < 2; ++c) {
        __syncthreads();                       // previous chunk's mma done

        if (tid < 512) {
            const int pt = tid & 63, mg = tid >> 6;    // mg 0..7
            const int gi = b * NPTS + n0 + c * 64 + pt;
            const float th = theta[gi], ph = phi[gi], ar = areas[gi];
            const float x = cosf(th);
            const float s = sqrtf(fmaxf(1.f - x * x, 0.f));
#pragma unroll
            for (int half = 0; half < 2; ++half) {
                const int m = half ? (15 - mg) : mg;
                float smv, cmv;
                sincosf((float)m * ph, &smv, &cmv);
                const float ca = cmv * ar, sa = smv * ar;
                float pmm = 1.f;
                for (int i = 1; i <= m; ++i) pmm *= -(2.f * i - 1.f) * s;
                int r = m * L1V - (m * (m - 1)) / 2;
                float pa = 0.f, pb = pmm;
                float f2 = 2.f * m + 1.f, fl = 2.f * m;
                for (int l = m; l < L1V; ++l) {
                    const float gc = pb * ca, gs = pb * sa;
                    __nv_bfloat16 chh, cll, shh, sll;
                    split_bf(gc, chh, cll);
                    split_bf(gs, shh, sll);
                    const int oc = SWZ((2 * r) * 128 + pt * 2);
                    const int os = SWZ((2 * r + 1) * 128 + pt * 2);
                    *(__nv_bfloat16*)(Ah + oc) = chh; *(__nv_bfloat16*)(Ah + os) = shh;
                    *(__nv_bfloat16*)(Al + oc) = cll; *(__nv_bfloat16*)(Al + os) = sll;
                    const float pn = (f2 * x * pb - fl * pa) * c_inv[l + 1 - m];
                    pa = pb; pb = pn; f2 += 2.f; fl += 1.f; ++r;
                }
            }
            // ---- B = V split, [pt][ch] SW128; 512 threads x 8 ch ----
            const int vp = tid >> 3, cseg = (tid & 7) * 8;
            const float4* vsrc =
                (const float4*)&values[((size_t)b * NPTS + n0 + c * 64 + vp) * CIN + cseg];
#pragma unroll
            for (int q = 0; q < 2; ++q) {
                float4 v = vsrc[q];
                __nv_bfloat16 h0, l0, h1, l1, h2, l2, h3, l3;
                split_bf(v.x, h0, l0); split_bf(v.y, h1, l1);
                split_bf(v.z, h2, l2); split_bf(v.w, h3, l3);
                const int ch = cseg + q * 4;
                const int o0 = SWZ(vp * 128 + ch * 2);
                const int o1 = SWZ(vp * 128 + (ch + 2) * 2);
                *(uint32_t*)(Bh + o0) = pack_bf2(__bfloat162float(h0), __bfloat162float(h1));
                *(uint32_t*)(Bh + o1) = pack_bf2(__bfloat162float(h2), __bfloat162float(h3));
                *(uint32_t*)(Bl + o0) = pack_bf2(__bfloat162float(l0), __bfloat162float(l1));
                *(uint32_t*)(Bl + o1) = pack_bf2(__bfloat162float(l2), __bfloat162float(l3));
            }
        }
        __syncthreads();

        // ---- warp MMA: warp owns rows 16*warp..+15 ----
        const int rowb = warp * 16;
#pragma unroll
        for (int kk = 0; kk < 4; ++kk) {
            uint32_t ah[4], al[4];
            const int aoff = SWZ((rowb + (lane & 15)) * 128 +
                                 (kk * 16 + 8 * (lane >> 4)) * 2);
            ldsm4(ah, AhU + aoff);
            ldsm4(al, AlU + aoff);
#pragma unroll
            for (int ntp = 0; ntp < 4; ++ntp) {
                uint32_t bh[4], bl[4];
                const int boff = SWZ((kk * 16 + 8 * ((lane >> 3) & 1) + (lane & 7)) * 128 +
                                     (ntp * 16 + 8 * (lane >> 4)) * 2);
                ldsm4t(bh, BhU + boff);
                ldsm4t(bl, BlU + boff);
                mma16816(acc[2 * ntp],     ah, bh);
                mma16816(acc[2 * ntp],     ah, bl);
                mma16816(acc[2 * ntp],     al, bh);
                mma16816(acc[2 * ntp + 1], ah, bh + 2);
                mma16816(acc[2 * ntp + 1], ah, bl + 2);
                mma16816(acc[2 * ntp + 1], al, bh + 2);
            }
        }
    }

    // ---- epilogue: shfl-pair -> float4 atomics (272 rows exact, no bounds) ----
    const int row = warp * 16 + (lane >> 2);
#pragma unroll
    for (int nt = 0; nt < 8; ++nt) {
        float* a = acc[nt];
        float o0 = __shfl_down_sync(0xffffffffu, a[0], 1);
        float o1 = __shfl_down_sync(0xffffffffu, a[1], 1);
        float o2 = __shfl_down_sync(0xffffffffu, a[2], 1);
        float o3 = __shfl_down_sync(0xffffffffu, a[3], 1);
        if ((lane & 1) == 0) {
            const int col = nt * 8 + (lane & 2) * 2;     // 0 or 4
            atomicAdd((float4*)&g_S[b][row][col], make_float4(a[0], a[1], o0, o1));
            atomicAdd((float4*)&g_S[b][row + 8][col], make_float4(a[2], a[3], o2, o3));
        }
    }
}

// ---------------- kernel 2: middle ----------------
__global__ __launch_bounds__(64)
void middle_kernel(const float* __restrict__ W)
{
    const int b = blockIdx.y;
    const int r = blockIdx.x;
    const int d = threadIdx.x;

    int m = 0, base = 0;
    while (base + (L1V - m) <= r) { base += L1V - m; ++m; }
    const int l = m + (r - base);

    double pre  = 2.0 * M_PI * sqrt(4.0 * M_PI / (2.0 * l + 1.0));
    double sph2 = (2.0 * l + 1.0) / (4.0 * M_PI);
    for (int k = l - m + 1; k <= l + m; ++k) sph2 /= (double)k;
    const float clm = (float)(pre * sph2);

    __shared__ float Sc[CIN], Ss[CIN];
    Sc[d] = g_S[b][2 * r][d];
    Ss[d] = g_S[b][2 * r + 1][d];
    __syncthreads();

    float are = 0.f, aim = 0.f;
    const float* Wl = W + l * CIN * COUT;
#pragma unroll 8
    for (int c = 0; c < CIN; ++c) {
        float w = Wl[c * COUT + d];
        are += Sc[c] * w;
        aim += Ss[c] * w;
    }
    are *=  clm;
    aim *= -clm;
    float rre = are > 0.f ? are : SLOPE * are;
    float rim = aim > 0.f ? aim : SLOPE * aim;
    const float fac = (m == 0) ? 1.f : 2.f;
    const float Tc =  fac * rre;
    const float Ts = -fac * rim;

    __nv_bfloat16 hc, lc, hs, ls;
    split_bf(Tc, hc, lc);
    split_bf(Ts, hs, ls);
    g_Tt[b][0][2 * r][d]     = *(uint16_t*)&hc;
    g_Tt[b][0][2 * r + 1][d] = *(uint16_t*)&hs;
    g_Tt[b][1][2 * r][d]     = *(uint16_t*)&lc;
    g_Tt[b][1][2 * r + 1][d] = *(uint16_t*)&ls;
}

// ---------------- kernel 3: synthesis ----------------
// out[pt][ch] = sum_k G[pt][k] * T[k][ch].  CTA: 128 pts, 512 threads (16 warps).
// Warp (ptile = w>>1 in 0..7) x (nhalf = w&1): 16 pts x 32 ch each -> full 128x64.
__global__ __launch_bounds__(512, 2)
void synthesis_kernel(const float* __restrict__ theta, const float* __restrict__ phi,
                      float* __restrict__ out)
{
    extern __shared__ __align__(1024) char sh[];
    char* Ah = sh;                 // 128*128 = 16384
    char* Al = sh + 16384;
    char* Bh = sh + 32768;         // 64*128 = 8192
    char* Bl = sh + 40960;         // total 49152
    const uint32_t AhU = smem_u32(Ah), AlU = smem_u32(Al);
    const uint32_t BhU = smem_u32(Bh), BlU = smem_u32(Bl);

    const int tid  = threadIdx.x;
    const int b    = blockIdx.y;
    const int n0   = blockIdx.x * 128;
    const int warp = tid >> 5, lane = tid & 31;
    const int ptile = warp >> 1, nhalf = warp & 1;

    // generator state (threads 0-127; thread = point)
    float x = 0.f, s = 0.f, sphi = 0.f, cphi = 0.f;
    float cm = 1.f, sm = 0.f, pmm = 1.f;
    float pa = 0.f, pb = 1.f, f2 = 1.f, fl = 0.f;
    int m = 0, l = 0, r = 0;
    if (tid < 128) {
        const int n = n0 + tid;
        const float th = theta[b * NPTS + n];
        const float ph = phi[b * NPTS + n];
        x = cosf(th);
        s = sqrtf(fmaxf(1.f - x * x, 0.f));
        sincosf(ph, &sphi, &cphi);
    }

    float acc[4][4];
#pragma unroll
    for (int j = 0; j < 4; ++j)
#pragma unroll
        for (int q = 0; q < 4; ++q) acc[j][q] = 0.f;

    for (int t = 0; t < 5; ++t) {
        __syncthreads();

        if (tid < 128) {
            // ---- generate 32 (cos,sin) k-pairs into A row ----
#pragma unroll
            for (int st = 0; st < 32; ++st) {
                const int off = SWZ(tid * 128 + st * 4);
                if (r < NLM) {
                    const float gc = pb * cm, gs = pb * sm;
                    __nv_bfloat16 chh, cll, shh, sll;
                    split_bf(gc, chh, cll);
                    split_bf(gs, shh, sll);
                    *(uint32_t*)(Ah + off) = pack_bf2(__bfloat162float(chh), __bfloat162float(shh));
                    *(uint32_t*)(Al + off) = pack_bf2(__bfloat162float(cll), __bfloat162float(sll));
                    const float pn = (f2 * x * pb - fl * pa) * c_inv[l + 1 - m];
                    pa = pb; pb = pn; f2 += 2.f; fl += 1.f; ++l; ++r;
                    if (l == L1V) {
                        pmm = -(2.f * m + 1.f) * s * pmm;
                        ++m; l = m;
                        const float cn = cm * cphi - sm * sphi;
                        sm = sm * cphi + cm * sphi; cm = cn;
                        pa = 0.f; pb = pmm;
                        f2 = 2.f * m + 1.f; fl = 2.f * m;
                    }
                } else {
                    *(uint32_t*)(Ah + off) = 0u;
                    *(uint32_t*)(Al + off) = 0u;
                }
            }
        } else if (tid < 256) {
            // ---- copy B chunk: 128 threads, one k-row of one split each ----
            const int loc = tid - 128;
            const int sp = loc >> 6, kr = loc & 63;
            const uint4* src = (const uint4*)&g_Tt[b][sp][t * 64 + kr][0];
            char* dst = sp ? Bl : Bh;
#pragma unroll
            for (int q = 0; q < 8; ++q)
                *(uint4*)(dst + SWZ(kr * 128 + q * 16)) = src[q];
        }
        __syncthreads();

        // ---- warp MMA: 16 pts x 32 ch per warp ----
        const int ptb = ptile * 16;
#pragma unroll
        for (int kk = 0; kk < 4; ++kk) {
            uint32_t ah[4], al[4];
            const int aoff = SWZ((ptb + (lane & 15)) * 128 +
                                 (kk * 16 + 8 * (lane >> 4)) * 2);
            ldsm4(ah, AhU + aoff);
            ldsm4(al, AlU + aoff);
#pragma unroll
            for (int j = 0; j < 2; ++j) {
                const int ntp = 2 * nhalf + j;
                uint32_t bh[4], bl[4];
                const int boff = SWZ((kk * 16 + 8 * ((lane >> 3) & 1) + (lane & 7)) * 128 +
                                     (ntp * 16 + 8 * (lane >> 4)) * 2);
                ldsm4t(bh, BhU + boff);
                ldsm4t(bl, BlU + boff);
                mma16816(acc[2 * j],     ah, bh);
                mma16816(acc[2 * j],     ah, bl);
                mma16816(acc[2 * j],     al, bh);
                mma16816(acc[2 * j + 1], ah, bh + 2);
                mma16816(acc[2 * j + 1], ah, bl + 2);
                mma16816(acc[2 * j + 1], al, bh + 2);
            }
        }
    }

    // ---- epilogue: write D fragments ----
    const int g = lane >> 2, t4 = lane & 3;
    float* o0 = &out[((size_t)b * NPTS + n0 + ptile * 16 + g) * COUT];
    float* o1 = &out[((size_t)b * NPTS + n0 + ptile * 16 + g + 8) * COUT];
#pragma unroll
    for (int q = 0; q < 4; ++q) {
        const int col = (2 * nhalf + (q >> 1)) * 16 + (q & 1) * 8 + 2 * t4;
        *(float2*)&o0[col] = make_float2(acc[q][0], acc[q][1]);
        *(float2*)&o1[col] = make_float2(acc[q][2], acc[q][3]);
    }
}

// ---------------- launch ----------------
extern "C" void kernel_launch(void* const* d_in, const int* in_sizes, int n_in,
                              void* d_out, int out_size)
{
    const float* theta  = (const float*)d_in[0];
    const float* phi    = (const float*)d_in[1];
    const float* areas  = (const float*)d_in[2];
    const float* values = (const float*)d_in[3];
    const float* W      = (const float*)d_in[4];
    float* out = (float*)d_out;

    const int an_smem = 86016;
    const int sy_smem = 49152;
    cudaFuncSetAttribute(analysis_kernel,
                         cudaFuncAttributeMaxDynamicSharedMemorySize, an_smem);
    cudaFuncSetAttribute(synthesis_kernel,
                         cudaFuncAttributeMaxDynamicSharedMemorySize, sy_smem);

    const int ztot = BB * SROWS * CIN + BB * 2 * KPAD * COUT / 2;
    zero_kernel<<<(ztot + 255) / 256, 256>>>();
    analysis_kernel<<<dim3(NPTS / 128, BB), 544, an_smem>>>(theta, phi, areas, values);
    middle_kernel<<<dim3(NLM, BB), 64>>>(W);
    synthesis_kernel<<<dim3(NPTS / 128, BB), 512, sy_smem>>>(theta, phi, out);
}

// round 9
// speedup vs baseline: 2.4616x; 1.1520x over previous
#include <cuda_runtime.h>
#include <cuda_bf16.h>
#include <math.h>
#include <stdint.h>

#define L1V   16
#define NLM   136
#define BB    4
#define NPTS  8192
#define CIN   64
#define COUT  64
#define SLOPE 0.01f
#define SROWS 272          // 17 m-tiles of 16, exact
#define KPAD  320          // synthesis K padded (5 chunks of 64)

// ---------------- scratch ----------------
__device__ float    g_S[BB][SROWS][CIN];
__device__ uint16_t g_Tt[BB][2][KPAD][COUT];   // bf16 [hi/lo][k][n]

__constant__ float c_inv[17] = {
    0.f, 1.f, 1.f/2.f, 1.f/3.f, 1.f/4.f, 1.f/5.f, 1.f/6.f, 1.f/7.f, 1.f/8.f,
    1.f/9.f, 1.f/10.f, 1.f/11.f, 1.f/12.f, 1.f/13.f, 1.f/14.f, 1.f/15.f, 1.f/16.f};

#define SWZ(o) ((o) ^ (((o) >> 3) & 0x70))

// ---------------- warp-MMA helpers ----------------
__device__ __forceinline__ uint32_t smem_u32(const void* p) {
    uint32_t a;
    asm("{ .reg .u64 t; cvta.to.shared.u64 t, %1; cvt.u32.u64 %0, t; }" : "=r"(a) : "l"(p));
    return a;
}
__device__ __forceinline__ void ldsm4(uint32_t* r, uint32_t addr) {
    asm volatile("ldmatrix.sync.aligned.m8n8.x4.shared.b16 {%0,%1,%2,%3}, [%4];"
        : "=r"(r[0]), "=r"(r[1]), "=r"(r[2]), "=r"(r[3]) : "r"(addr));
}
__device__ __forceinline__ void ldsm4t(uint32_t* r, uint32_t addr) {
    asm volatile("ldmatrix.sync.aligned.m8n8.x4.trans.shared.b16 {%0,%1,%2,%3}, [%4];"
        : "=r"(r[0]), "=r"(r[1]), "=r"(r[2]), "=r"(r[3]) : "r"(addr));
}
__device__ __forceinline__ void mma16816(float* d, const uint32_t* a, const uint32_t* b) {
    asm volatile(
        "mma.sync.aligned.m16n8k16.row.col.f32.bf16.bf16.f32 "
        "{%0,%1,%2,%3}, {%4,%5,%6,%7}, {%8,%9}, {%0,%1,%2,%3};"
        : "+f"(d[0]), "+f"(d[1]), "+f"(d[2]), "+f"(d[3])
        : "r"(a[0]), "r"(a[1]), "r"(a[2]), "r"(a[3]), "r"(b[0]), "r"(b[1]));
}
__device__ __forceinline__ uint32_t pack_bf2(float a, float b) {
    __nv_bfloat162 h = __floats2bfloat162_rn(a, b);      // low half = a
    return *(uint32_t*)&h;
}
__device__ __forceinline__ void split_bf(float g, __nv_bfloat16& hi, __nv_bfloat16& lo) {
    hi = __float2bfloat16_rn(g);
    lo = __float2bfloat16_rn(g - __bfloat162float(hi));
}

// ---------------- kernel 0: zero scratch ----------------
__global__ void zero_kernel() {
    int i = blockIdx.x * blockDim.x + threadIdx.x;
    const int NS = BB * SROWS * CIN;                 // 69632 floats
    const int NT = BB * 2 * KPAD * COUT / 2;         // 81920 u32
    if (i < NS) ((float*)g_S)[i] = 0.f;
    else if (i < NS + NT) ((uint32_t*)g_Tt)[i - NS] = 0u;
}

// ---------------- kernel 1: analysis ----------------
// S[row][ch] += sum_pt G^T[row][pt] * V[pt][ch].  CTA: 128 pts (2 chunks of 64),
// 544 threads = 17 warps x 16 rows.  Gen: 512 threads, (pt, mg) with m in {mg, 15-mg}
// -> exactly 17 recursion steps per thread.  (544,2): cap regs for 2 CTAs/SM.
__global__ __launch_bounds__(544, 2)
void analysis_kernel(const float* __restrict__ theta, const float* __restrict__ phi,
                     const float* __restrict__ areas, const float* __restrict__ values)
{
    extern __shared__ __align__(1024) char sh[];
    char* Ah = sh;                 // 272*128 = 34816
    char* Al = sh + 34816;
    char* Bh = sh + 69632;         // 64*128 = 8192
    char* Bl = sh + 77824;         // total 86016
    const uint32_t AhU = smem_u32(Ah), AlU = smem_u32(Al);
    const uint32_t BhU = smem_u32(Bh), BlU = smem_u32(Bl);

    const int tid  = threadIdx.x;
    const int b    = blockIdx.y;
    const int n0   = blockIdx.x * 128;
    const int warp = tid >> 5, lane = tid & 31;

    float acc[8][4];
#pragma unroll
    for (int j = 0; j < 8; ++j)
#pragma unroll
        for (int q = 0; q < 4; ++q) acc[j][q] = 0.f;

    for (int c = 0; c < 2; ++c) {
        __syncthreads();                       // previous chunk's mma done

        if (tid < 512) {
            const int pt = tid & 63, mg = tid >> 6;    // mg 0..7
            const int gi = b * NPTS + n0 + c * 64 + pt;
            const float th = theta[gi], ph = phi[gi], ar = areas[gi];
            const float x = cosf(th);
            const float s = sqrtf(fmaxf(1.f - x * x, 0.f));
#pragma unroll
            for (int half = 0; half < 2; ++half) {
                const int m = half ? (15 - mg) : mg;
                float smv, cmv;
                sincosf((float)m * ph, &smv, &cmv);
                const float ca = cmv * ar, sa = smv * ar;
                float pmm = 1.f;
                for (int i = 1; i <= m; ++i) pmm *= -(2.f * i - 1.f) * s;
                int r = m * L1V - (m * (m - 1)) / 2;
                float pa = 0.f, pb = pmm;
                float f2 = 2.f * m + 1.f, fl = 2.f * m;
                for (int l = m; l < L1V; ++l) {
                    const float gc = pb * ca, gs = pb * sa;
                    __nv_bfloat16 chh, cll, shh, sll;
                    split_bf(gc, chh, cll);
                    split_bf(gs, shh, sll);
                    const int oc = SWZ((2 * r) * 128 + pt * 2);
                    const int os = SWZ((2 * r + 1) * 128 + pt * 2);
                    *(__nv_bfloat16*)(Ah + oc) = chh; *(__nv_bfloat16*)(Ah + os) = shh;
                    *(__nv_bfloat16*)(Al + oc) = cll; *(__nv_bfloat16*)(Al + os) = sll;
                    const float pn = (f2 * x * pb - fl * pa) * c_inv[l + 1 - m];
                    pa = pb; pb = pn; f2 += 2.f; fl += 1.f; ++r;
                }
            }
            // ---- B = V split, [pt][ch] SW128; 512 threads x 8 ch ----
            const int vp = tid >> 3, cseg = (tid & 7) * 8;
            const float4* vsrc =
                (const float4*)&values[((size_t)b * NPTS + n0 + c * 64 + vp) * CIN + cseg];
#pragma unroll
            for (int q = 0; q < 2; ++q) {
                float4 v = vsrc[q];
                __nv_bfloat16 h0, l0, h1, l1, h2, l2, h3, l3;
                split_bf(v.x, h0, l0); split_bf(v.y, h1, l1);
                split_bf(v.z, h2, l2); split_bf(v.w, h3, l3);
                const int ch = cseg + q * 4;
                const int o0 = SWZ(vp * 128 + ch * 2);
                const int o1 = SWZ(vp * 128 + (ch + 2) * 2);
                *(uint32_t*)(Bh + o0) = pack_bf2(__bfloat162float(h0), __bfloat162float(h1));
                *(uint32_t*)(Bh + o1) = pack_bf2(__bfloat162float(h2), __bfloat162float(h3));
                *(uint32_t*)(Bl + o0) = pack_bf2(__bfloat162float(l0), __bfloat162float(l1));
                *(uint32_t*)(Bl + o1) = pack_bf2(__bfloat162float(l2), __bfloat162float(l3));
            }
        }
        __syncthreads();

        // ---- warp MMA: warp owns rows 16*warp..+15 ----
        const int rowb = warp * 16;
#pragma unroll
        for (int kk = 0; kk < 4; ++kk) {
            uint32_t ah[4], al[4];
            const int aoff = SWZ((rowb + (lane & 15)) * 128 +
                                 (kk * 16 + 8 * (lane >> 4)) * 2);
            ldsm4(ah, AhU + aoff);
            ldsm4(al, AlU + aoff);
#pragma unroll
            for (int ntp = 0; ntp < 4; ++ntp) {
                uint32_t bh[4], bl[4];
                const int boff = SWZ((kk * 16 + 8 * ((lane >> 3) & 1) + (lane & 7)) * 128 +
                                     (ntp * 16 + 8 * (lane >> 4)) * 2);
                ldsm4t(bh, BhU + boff);
                ldsm4t(bl, BlU + boff);
                mma16816(acc[2 * ntp],     ah, bh);
                mma16816(acc[2 * ntp],     ah, bl);
                mma16816(acc[2 * ntp],     al, bh);
                mma16816(acc[2 * ntp + 1], ah, bh + 2);
                mma16816(acc[2 * ntp + 1], ah, bl + 2);
                mma16816(acc[2 * ntp + 1], al, bh + 2);
            }
        }
    }

    // ---- epilogue: shfl-pair -> float4 atomics (272 rows exact, no bounds) ----
    const int row = warp * 16 + (lane >> 2);
#pragma unroll
    for (int nt = 0; nt < 8; ++nt) {
        float* a = acc[nt];
        float o0 = __shfl_down_sync(0xffffffffu, a[0], 1);
        float o1 = __shfl_down_sync(0xffffffffu, a[1], 1);
        float o2 = __shfl_down_sync(0xffffffffu, a[2], 1);
        float o3 = __shfl_down_sync(0xffffffffu, a[3], 1);
        if ((lane & 1) == 0) {
            const int col = nt * 8 + (lane & 2) * 2;     // 0 or 4
            atomicAdd((float4*)&g_S[b][row][col], make_float4(a[0], a[1], o0, o1));
            atomicAdd((float4*)&g_S[b][row + 8][col], make_float4(a[2], a[3], o2, o3));
        }
    }
}

// ---------------- kernel 2: middle ----------------
__global__ __launch_bounds__(64)
void middle_kernel(const float* __restrict__ W)
{
    const int b = blockIdx.y;
    const int r = blockIdx.x;
    const int d = threadIdx.x;

    int m = 0, base = 0;
    while (base + (L1V - m) <= r) { base += L1V - m; ++m; }
    const int l = m + (r - base);

    double pre  = 2.0 * M_PI * sqrt(4.0 * M_PI / (2.0 * l + 1.0));
    double sph2 = (2.0 * l + 1.0) / (4.0 * M_PI);
    for (int k = l - m + 1; k <= l + m; ++k) sph2 /= (double)k;
    const float clm = (float)(pre * sph2);

    __shared__ float Sc[CIN], Ss[CIN];
    Sc[d] = g_S[b][2 * r][d];
    Ss[d] = g_S[b][2 * r + 1][d];
    __syncthreads();

    float are = 0.f, aim = 0.f;
    const float* Wl = W + l * CIN * COUT;
#pragma unroll 8
    for (int c = 0; c < CIN; ++c) {
        float w = Wl[c * COUT + d];
        are += Sc[c] * w;
        aim += Ss[c] * w;
    }
    are *=  clm;
    aim *= -clm;
    float rre = are > 0.f ? are : SLOPE * are;
    float rim = aim > 0.f ? aim : SLOPE * aim;
    const float fac = (m == 0) ? 1.f : 2.f;
    const float Tc =  fac * rre;
    const float Ts = -fac * rim;

    __nv_bfloat16 hc, lc, hs, ls;
    split_bf(Tc, hc, lc);
    split_bf(Ts, hs, ls);
    g_Tt[b][0][2 * r][d]     = *(uint16_t*)&hc;
    g_Tt[b][0][2 * r + 1][d] = *(uint16_t*)&hs;
    g_Tt[b][1][2 * r][d]     = *(uint16_t*)&lc;
    g_Tt[b][1][2 * r + 1][d] = *(uint16_t*)&ls;
}

// ---------------- kernel 3: synthesis ----------------
// out[pt][ch] = sum_k G[pt][k] * T[k][ch].  CTA: 128 pts, 512 threads (16 warps).
// Warp (ptile = w>>1 in 0..7) x (nhalf = w&1).  Double-buffered A/B, one barrier
// per chunk; gen batches 4 steps into conflict-free STS.128.
#define SY_BUF 49152       // per-buffer: Ah 16384 | Al 16384 | Bh 8192 | Bl 8192

__global__ __launch_bounds__(512, 2)
void synthesis_kernel(const float* __restrict__ theta, const float* __restrict__ phi,
                      float* __restrict__ out)
{
    extern __shared__ __align__(1024) char sh[];
    const int tid  = threadIdx.x;
    const int b    = blockIdx.y;
    const int n0   = blockIdx.x * 128;
    const int warp = tid >> 5, lane = tid & 31;
    const int ptile = warp >> 1, nhalf = warp & 1;

    // generator state (threads 0-127; thread = point)
    float x = 0.f, s = 0.f, sphi = 0.f, cphi = 0.f;
    float cm = 1.f, sm = 0.f, pmm = 1.f;
    float pa = 0.f, pb = 1.f, f2 = 1.f, fl = 0.f;
    int m = 0, l = 0, r = 0;
    if (tid < 128) {
        const int n = n0 + tid;
        const float th = theta[b * NPTS + n];
        const float ph = phi[b * NPTS + n];
        x = cosf(th);
        s = sqrtf(fmaxf(1.f - x * x, 0.f));
        sincosf(ph, &sphi, &cphi);
    }

    // emit 32 (cos,sin) k-pairs, batched 4 steps -> 1 STS.128 per split
    auto emit32 = [&](char* base) {
        char* AhD = base;
        char* AlD = base + 16384;
#pragma unroll
        for (int g8 = 0; g8 < 8; ++g8) {
            uint32_t vh[4], vl[4];
#pragma unroll
            for (int q = 0; q < 4; ++q) {
                if (r < NLM) {
                    const float gc = pb * cm, gs = pb * sm;
                    __nv_bfloat16 chh, cll, shh, sll;
                    split_bf(gc, chh, cll);
                    split_bf(gs, shh, sll);
                    vh[q] = pack_bf2(__bfloat162float(chh), __bfloat162float(shh));
                    vl[q] = pack_bf2(__bfloat162float(cll), __bfloat162float(sll));
                    const float pn = (f2 * x * pb - fl * pa) * c_inv[l + 1 - m];
                    pa = pb; pb = pn; f2 += 2.f; fl += 1.f; ++l; ++r;
                    if (l == L1V) {
                        pmm = -(2.f * m + 1.f) * s * pmm;
                        ++m; l = m;
                        const float cn = cm * cphi - sm * sphi;
                        sm = sm * cphi + cm * sphi; cm = cn;
                        pa = 0.f; pb = pmm;
                        f2 = 2.f * m + 1.f; fl = 2.f * m;
                    }
                } else { vh[q] = 0u; vl[q] = 0u; }
            }
            const int off = SWZ(tid * 128 + g8 * 16);
            *(uint4*)(AhD + off) = make_uint4(vh[0], vh[1], vh[2], vh[3]);
            *(uint4*)(AlD + off) = make_uint4(vl[0], vl[1], vl[2], vl[3]);
        }
    };
    // copy B chunk t: threads 128-383, 4 uint4 each
    auto copyB = [&](char* base, int t) {
        const int loc = tid - 128;            // 0..255
        const int sp = loc >> 7;              // 0 hi, 1 lo
        const int kr = (loc >> 1) & 63;
        const int hf = loc & 1;
        const uint4* src = (const uint4*)&g_Tt[b][sp][t * 64 + kr][0];
        char* dst = base + 32768 + sp * 8192;
#pragma unroll
        for (int q = 0; q < 4; ++q)
            *(uint4*)(dst + SWZ(kr * 128 + (hf * 4 + q) * 16)) = src[hf * 4 + q];
    };

    float acc[4][4];
#pragma unroll
    for (int j = 0; j < 4; ++j)
#pragma unroll
        for (int q = 0; q < 4; ++q) acc[j][q] = 0.f;

    if (tid < 128) emit32(sh);
    else if (tid < 384) copyB(sh, 0);
    __syncthreads();

    for (int t = 0; t < 5; ++t) {
        char* buf = sh + (t & 1) * SY_BUF;
        char* nxt = sh + ((t + 1) & 1) * SY_BUF;
        if (t < 4) {
            if (tid < 128) emit32(nxt);
            else if (tid < 384) copyB(nxt, t + 1);
        }

        const uint32_t AhU = smem_u32(buf);
        const uint32_t AlU = AhU + 16384;
        const uint32_t BhU = AhU + 32768;
        const uint32_t BlU = AhU + 40960;
        const int ptb = ptile * 16;
#pragma unroll
        for (int kk = 0; kk < 4; ++kk) {
            uint32_t ah[4], al[4];
            const int aoff = SWZ((ptb + (lane & 15)) * 128 +
                                 (kk * 16 + 8 * (lane >> 4)) * 2);
            ldsm4(ah, AhU + aoff);
            ldsm4(al, AlU + aoff);
#pragma unroll
            for (int j = 0; j < 2; ++j) {
                const int ntp = 2 * nhalf + j;
                uint32_t bh[4], bl[4];
                const int boff = SWZ((kk * 16 + 8 * ((lane >> 3) & 1) + (lane & 7)) * 128 +
                                     (ntp * 16 + 8 * (lane >> 4)) * 2);
                ldsm4t(bh, BhU + boff);
                ldsm4t(bl, BlU + boff);
                mma16816(acc[2 * j],     ah, bh);
                mma16816(acc[2 * j],     ah, bl);
                mma16816(acc[2 * j],     al, bh);
                mma16816(acc[2 * j + 1], ah, bh + 2);
                mma16816(acc[2 * j + 1], ah, bl + 2);
                mma16816(acc[2 * j + 1], al, bh + 2);
            }
        }
        __syncthreads();
    }

    // ---- epilogue: write D fragments ----
    const int g = lane >> 2, t4 = lane & 3;
    float* o0 = &out[((size_t)b * NPTS + n0 + ptile * 16 + g) * COUT];
    float* o1 = &out[((size_t)b * NPTS + n0 + ptile * 16 + g + 8) * COUT];
#pragma unroll
    for (int q = 0; q < 4; ++q) {
        const int col = (2 * nhalf + (q >> 1)) * 16 + (q & 1) * 8 + 2 * t4;
        *(float2*)&o0[col] = make_float2(acc[q][0], acc[q][1]);
        *(float2*)&o1[col] = make_float2(acc[q][2], acc[q][3]);
    }
}

// ---------------- launch ----------------
extern "C" void kernel_launch(void* const* d_in, const int* in_sizes, int n_in,
                              void* d_out, int out_size)
{
    const float* theta  = (const float*)d_in[0];
    const float* phi    = (const float*)d_in[1];
    const float* areas  = (const float*)d_in[2];
    const float* values = (const float*)d_in[3];
    const float* W      = (const float*)d_in[4];
    float* out = (float*)d_out;

    const int an_smem = 86016;
    const int sy_smem = 2 * SY_BUF;     // 98304
    cudaFuncSetAttribute(analysis_kernel,
                         cudaFuncAttributeMaxDynamicSharedMemorySize, an_smem);
    cudaFuncSetAttribute(synthesis_kernel,
                         cudaFuncAttributeMaxDynamicSharedMemorySize, sy_smem);

    const int ztot = BB * SROWS * CIN + BB * 2 * KPAD * COUT / 2;
    zero_kernel<<<(ztot + 255) / 256, 256>>>();
    analysis_kernel<<<dim3(NPTS / 128, BB), 544, an_smem>>>(theta, phi, areas, values);
    middle_kernel<<<dim3(NLM, BB), 64>>>(W);
    synthesis_kernel<<<dim3(NPTS / 128, BB), 512, sy_smem>>>(theta, phi, out);
}